// round 9
// baseline (speedup 1.0000x reference)
#include <cuda_runtime.h>
#include <cstdint>

#define B_   256
#define T_   100
#define NIN  700
#define KP   704            // NIN padded to multiple of 16
#define NN   2068
#define NNP  2176           // NN padded to multiple of 64
#define NOUT 20
#define TAU  0.6f
#define KC   320            // Eigen kc panel size
#define MROWS (B_ * T_)     // 25600

// GEMM tile geometry (warp-specialized half-CTA: 256 threads)
#define BM 128
#define BN 64
#define BK 8
#define COLB   (NNP / BN)        // 34 col blocks
#define TPT    (3 * COLB * 2)    // 204 tiles per timestep (3 slabs x 34 cols x 2 row halves)
#define NTILES (T_ * TPT)        // 20400

#define CPT 9                    // steps: j=0..7 full (n=j*256+htid), j=8 only htid<20
#define NWP 8
#define NHELP 40

// ---------------- scratch (device globals; no runtime allocation) ----------
__device__ float g_ffp[3][(size_t)MROWS * NNP];  // per-panel ff partials
__device__ float g_xp[(size_t)MROWS * KP];       // x staged [r=t*B+b][k], zero-padded
__device__ float g_w1t[(size_t)KP * NNP];        // W_fc1^T zero-padded [k][n]
__device__ unsigned g_next;                      // GEMM tile steal counter
__device__ unsigned g_done[T_];                  // per-timestep completed tiles

#define BARG() asm volatile("bar.sync 1, 256;" ::: "memory")
#define BARS() asm volatile("bar.sync 2, 256;" ::: "memory")

// ---------------- staging ---------------------------------------------------
__global__ void zero_ctrl_kernel() {
    int i = threadIdx.x;
    if (i < T_) g_done[i] = 0u;
    if (i == T_) g_next = 0u;
}

__global__ void pad_x_kernel(const float* __restrict__ x) {
    size_t idx = (size_t)blockIdx.x * blockDim.x + threadIdx.x;
    if (idx < (size_t)MROWS * KP) {
        int r = (int)(idx / KP);
        int k = (int)(idx - (size_t)r * KP);
        int t = r >> 8;
        int b = r & 255;
        g_xp[idx] = (k < NIN) ? x[((size_t)b * T_ + t) * NIN + k] : 0.0f;
    }
}

__global__ void pad_w1t_kernel(const float* __restrict__ W1) {
    size_t idx = (size_t)blockIdx.x * blockDim.x + threadIdx.x;
    if (idx < (size_t)KP * NNP) {
        int k = (int)(idx / NNP);
        int n = (int)(idx - (size_t)k * NNP);
        g_w1t[idx] = (k < NIN && n < NN) ? W1[(size_t)n * NIN + k] : 0.0f;
    }
}

// ---------------- shared memory ----------------------------------------------
struct SM {
    float As[2][BK][BM];     // 8 KB
    float Bs[2][BK][BN];     // 4 KB
    unsigned tile;           // GEMM-half broadcast
    unsigned ready;          // steps-half broadcast
    int wcnt[CPT][NWP];
    int list[NN];            // ~8.3 KB
};

// ---------------- one GEMM tile (double-buffered, named-barrier synced) ------
// Per output element: one sequential-k FMA chain over its slab == Eigen panel.
__device__ __forceinline__ void do_tile(unsigned n, SM* sm, int htid) {
    unsigned tt = n / TPT;
    unsigned r  = n % TPT;
    unsigned z  = r / (COLB * 2u);
    unsigned r2 = r % (COLB * 2u);
    int col0 = (int)(r2 >> 1) * BN;
    int row0 = (int)tt * 256 + (int)(r2 & 1u) * BM;
    int k0g  = (int)z * KC;
    int KL   = (z == 2u) ? (KP - 2 * KC) : KC;
    int nT   = KL / BK;

    float* C = g_ffp[0] + (size_t)z * MROWS * NNP;

    int arow = htid >> 1;
    int asub = (htid & 1) * 4;
    const float* ap = g_xp + (size_t)(row0 + arow) * KP + k0g + asub;

    int bn   = htid & 63;
    int ksub = (htid >> 6) * 2;
    const float* bp = g_w1t + (size_t)(k0g + ksub) * NNP + (col0 + bn);

    int tr = (htid >> 4) * 8;
    int tc = (htid & 15) * 4;

    float4 ra;
    float  rb0, rb1;

    ra  = *(const float4*)(ap);
    rb0 = bp[0];
    rb1 = bp[NNP];

    sm->As[0][asub + 0][arow] = ra.x; sm->As[0][asub + 1][arow] = ra.y;
    sm->As[0][asub + 2][arow] = ra.z; sm->As[0][asub + 3][arow] = ra.w;
    sm->Bs[0][ksub + 0][bn] = rb0;
    sm->Bs[0][ksub + 1][bn] = rb1;
    BARG();

    float acc[8][4];
    #pragma unroll
    for (int i = 0; i < 8; i++)
        #pragma unroll
        for (int j = 0; j < 4; j++) acc[i][j] = 0.0f;

    for (int tI = 0; tI < nT; tI++) {
        int  buf  = tI & 1;
        bool more = (tI + 1 < nT);

        if (more) {
            ra  = *(const float4*)(ap + (tI + 1) * BK);
            const float* bpn = bp + (size_t)(tI + 1) * BK * NNP;
            rb0 = bpn[0];
            rb1 = bpn[NNP];
        }

        #pragma unroll
        for (int kk = 0; kk < BK; kk++) {
            float a[8], bv[4];
            *(float4*)&a[0] = *(const float4*)&sm->As[buf][kk][tr];
            *(float4*)&a[4] = *(const float4*)&sm->As[buf][kk][tr + 4];
            *(float4*)&bv[0] = *(const float4*)&sm->Bs[buf][kk][tc];
            #pragma unroll
            for (int i = 0; i < 8; i++)
                #pragma unroll
                for (int j = 0; j < 4; j++)
                    acc[i][j] = __fmaf_rn(a[i], bv[j], acc[i][j]);
        }

        if (more) {
            int nb = buf ^ 1;
            sm->As[nb][asub + 0][arow] = ra.x; sm->As[nb][asub + 1][arow] = ra.y;
            sm->As[nb][asub + 2][arow] = ra.z; sm->As[nb][asub + 3][arow] = ra.w;
            sm->Bs[nb][ksub + 0][bn] = rb0;
            sm->Bs[nb][ksub + 1][bn] = rb1;
        }
        BARG();
    }

    #pragma unroll
    for (int i = 0; i < 8; i++)
        *(float4*)(C + (size_t)(row0 + tr + i) * NNP + (col0 + tc)) = *(float4*)&acc[i][0];

    __threadfence();           // release C stores (per thread)
    BARG();                    // all threads fenced
    if (htid == 0) atomicAdd(&g_done[tt], 1u);
}

// ---------------- fused warp-specialized kernel -------------------------------
__global__ __launch_bounds__(512, 2) void fused_kernel(const float* __restrict__ Wrec,
                                                       float* __restrict__ out) {
    __shared__ SM sm;

    int bid  = blockIdx.x;
    int half = threadIdx.x >> 8;     // 0 = GEMM worker, 1 = steps
    int htid = threadIdx.x & 255;

    if (half == 0) {
        // ---- GEMM worker half: drain ascending-t tile queue ----
        for (;;) {
            if (htid == 0) sm.tile = atomicAdd(&g_next, 1u);
            BARG();
            unsigned n = sm.tile;
            BARG();
            if (n >= NTILES) return;
            do_tile(n, &sm, htid);
        }
    }

    // ---- steps half ----
    if (bid >= B_) return;           // helper CTA: no steps role
    int b    = bid;
    int wid  = htid >> 5;
    int lane = htid & 31;
    unsigned ltmask = (1u << lane) - 1u;
    bool tv  = (htid < NOUT);

    float m[CPT], s[CPT];
    #pragma unroll
    for (int j = 0; j < CPT; j++) { m[j] = 0.0f; s[j] = 0.0f; }

    const float* ff0 = g_ffp[0];
    const float* ff1 = g_ffp[1];
    const float* ff2 = g_ffp[2];

    for (int t = 0; t < T_; t++) {
        // ---- wait for ff[t] completion (poll per-t counter) ----
        for (;;) {
            if (htid == 0)
                sm.ready = (*(volatile unsigned*)&g_done[t] >= TPT) ? 1u : 0u;
            BARS();
            unsigned rd = sm.ready;
            BARS();
            if (rd) break;
            __nanosleep(200);
        }
        __threadfence();   // acquire: order ff reads after observed completion

        // ---- build ascending active list (ballot + cross-warp prefix) ----
        unsigned msk[CPT];
        #pragma unroll
        for (int j = 0; j < CPT; j++) {
            bool a = ((j < 8) || tv) && (s[j] != 0.0f);
            msk[j] = __ballot_sync(0xffffffffu, a);
            if (lane == 0) sm.wcnt[j][wid] = __popc(msk[j]);
        }
        BARS();

        int base[CPT];
        int cnt;
        {
            int rb = 0;
            #pragma unroll
            for (int jj = 0; jj < CPT; jj++) {
                int off = 0, rowtot = 0;
                #pragma unroll
                for (int w = 0; w < NWP; w++) {
                    int c = sm.wcnt[jj][w];
                    if (w < wid) off += c;
                    rowtot += c;
                }
                base[jj] = rb + off;
                rb += rowtot;
            }
            cnt = rb;
        }

        #pragma unroll
        for (int j = 0; j < CPT; j++) {
            bool a = ((j < 8) || tv) && (s[j] != 0.0f);
            if (a) sm.list[base[j] + __popc(msk[j] & ltmask)] = j * 256 + htid;
        }
        BARS();

        // ---- rec: kc=320-panel fold of ascending active-row adds (unroll-2) ----
        float rec[CPT], part[CPT];
        #pragma unroll
        for (int j = 0; j < CPT; j++) { rec[j] = 0.0f; part[j] = 0.0f; }

        int curp = 0;
        int i = 0;
        for (; i + 2 <= cnt; i += 2) {
            int m0 = sm.list[i + 0], m1 = sm.list[i + 1];
            const float* w0 = Wrec + (size_t)m0 * NN;
            const float* w1 = Wrec + (size_t)m1 * NN;
            float v0[CPT], v1[CPT];
            #pragma unroll
            for (int j = 0; j < CPT; j++) {
                int n = j * 256 + htid;
                bool v = (j < 8) || tv;
                v0[j] = v ? w0[n] : 0.0f;
                v1[j] = v ? w1[n] : 0.0f;
            }
            int p = m0 / KC;
            if (p != curp) {
                #pragma unroll
                for (int j = 0; j < CPT; j++) { rec[j] = __fadd_rn(rec[j], part[j]); part[j] = 0.0f; }
                curp = p;
            }
            #pragma unroll
            for (int j = 0; j < CPT; j++) part[j] = __fadd_rn(part[j], v0[j]);
            p = m1 / KC;
            if (p != curp) {
                #pragma unroll
                for (int j = 0; j < CPT; j++) { rec[j] = __fadd_rn(rec[j], part[j]); part[j] = 0.0f; }
                curp = p;
            }
            #pragma unroll
            for (int j = 0; j < CPT; j++) part[j] = __fadd_rn(part[j], v1[j]);
        }
        for (; i < cnt; i++) {
            int mr = sm.list[i];
            const float* wr = Wrec + (size_t)mr * NN;
            float v0[CPT];
            #pragma unroll
            for (int j = 0; j < CPT; j++) {
                int n = j * 256 + htid;
                v0[j] = ((j < 8) || tv) ? wr[n] : 0.0f;
            }
            int p = mr / KC;
            if (p != curp) {
                #pragma unroll
                for (int j = 0; j < CPT; j++) { rec[j] = __fadd_rn(rec[j], part[j]); part[j] = 0.0f; }
                curp = p;
            }
            #pragma unroll
            for (int j = 0; j < CPT; j++) part[j] = __fadd_rn(part[j], v0[j]);
        }
        #pragma unroll
        for (int j = 0; j < CPT; j++) rec[j] = __fadd_rn(rec[j], part[j]);

        // ---- membrane update + spikes (unfused, reference order) ----
        size_t rbase = ((size_t)t * B_ + b) * NNP;
        #pragma unroll
        for (int j = 0; j < CPT; j++) {
            if ((j < 8) || tv) {
                int n = j * 256 + htid;
                float ffv = __fadd_rn(__fadd_rn(ff0[rbase + n], ff1[rbase + n]), ff2[rbase + n]);
                float cur = __fadd_rn(ffv, rec[j]);
                float t1  = __fmul_rn(TAU, m[j]);
                float t2  = __fsub_rn(1.0f, s[j]);
                float t3  = __fmul_rn(t1, t2);
                float mn  = __fadd_rn(t3, cur);
                m[j] = mn;
                s[j] = (mn >= 1.0f) ? 1.0f : 0.0f;
            }
        }
        if (tv)
            out[((size_t)b * T_ + t) * NOUT + htid] = s[8];

        BARS();   // protect sm.list/wcnt reuse next step
    }
}

// ---------------- launch -----------------------------------------------------
extern "C" void kernel_launch(void* const* d_in, const int* in_sizes, int n_in,
                              void* d_out, int out_size) {
    const float* x  = (const float*)d_in[0];   // [B, T, NIN]
    const float* W1 = (const float*)d_in[1];   // [NN, NIN]
    const float* Wr = (const float*)d_in[2];   // [NN, NN]
    float* out = (float*)d_out;                // [B, T, NOUT]

    zero_ctrl_kernel<<<1, 128>>>();
    {
        size_t n = (size_t)MROWS * KP;
        pad_x_kernel<<<(unsigned)((n + 255) / 256), 256>>>(x);
    }
    {
        size_t n = (size_t)KP * NNP;
        pad_w1t_kernel<<<(unsigned)((n + 255) / 256), 256>>>(W1);
    }

    fused_kernel<<<B_ + NHELP, 512>>>(Wr, out);
}

// round 10
// speedup vs baseline: 1.3169x; 1.3169x over previous
#include <cuda_runtime.h>
#include <cstdint>

#define B_   256
#define T_   100
#define NIN  700
#define KP   704            // NIN padded to multiple of 16
#define NN   2068
#define NNP  2176           // NN padded to multiple of 128
#define NOUT 20
#define TAU  0.6f
#define KC   320            // Eigen kc panel size
#define MROWS (B_ * T_)     // 25600

// ---------------- scratch (device globals; no runtime allocation) ----------
__device__ float g_ffp[3][(size_t)MROWS * NNP];  // per-panel ff partials
__device__ float g_xp[(size_t)MROWS * KP];       // x staged: [r = t*B+b][k], zero-padded
__device__ float g_w1t[(size_t)KP * NNP];        // W_fc1^T zero-padded: [k][n]

// ---------------- staging ---------------------------------------------------
__global__ void pad_x_kernel(const float* __restrict__ x) {
    size_t idx = (size_t)blockIdx.x * blockDim.x + threadIdx.x;
    if (idx < (size_t)MROWS * KP) {
        int r = (int)(idx / KP);
        int k = (int)(idx - (size_t)r * KP);
        int t = r >> 8;                 // r = t*256 + b
        int b = r & 255;
        g_xp[idx] = (k < NIN) ? x[((size_t)b * T_ + t) * NIN + k] : 0.0f;
    }
}

__global__ void pad_w1t_kernel(const float* __restrict__ W1) {
    size_t idx = (size_t)blockIdx.x * blockDim.x + threadIdx.x;
    if (idx < (size_t)KP * NNP) {
        int k = (int)(idx / NNP);
        int n = (int)(idx - (size_t)k * NNP);
        g_w1t[idx] = (k < NIN && n < NN) ? W1[(size_t)n * NIN + k] : 0.0f;
    }
}

// ---------------- phase 1: per-panel GEMM slabs (R6, double-buffered FFMA) --
#define BM 128
#define BN 128
#define BK 16

__global__ __launch_bounds__(256, 2) void gemm_slab_kernel() {
    __shared__ float As[2][BK][BM];
    __shared__ float Bs[2][BK][BN];

    int tid  = threadIdx.x;
    int z    = blockIdx.z;
    int row0 = blockIdx.y * BM;
    int col0 = blockIdx.x * BN;
    int k0g  = z * KC;
    int KL   = (z == 2) ? (KP - 2 * KC) : KC;
    int nT   = KL / BK;

    float* C = g_ffp[0] + (size_t)z * MROWS * NNP;

    int arow = tid >> 1;
    int asub = (tid & 1) * 8;
    const float* ap = g_xp + (size_t)(row0 + arow) * KP + k0g + asub;

    int bn   = tid & 127;
    int bsub = (tid >> 7) * 8;
    const float* bp = g_w1t + (size_t)(k0g + bsub) * NNP + (col0 + bn);

    int tr = (tid >> 4) * 8;
    int tc = (tid & 15) * 8;

    float4 ra0, ra1;
    float  rbv[8];

    ra0 = *(const float4*)(ap);
    ra1 = *(const float4*)(ap + 4);
    #pragma unroll
    for (int i = 0; i < 8; i++) rbv[i] = bp[(size_t)i * NNP];

    As[0][asub + 0][arow] = ra0.x; As[0][asub + 1][arow] = ra0.y;
    As[0][asub + 2][arow] = ra0.z; As[0][asub + 3][arow] = ra0.w;
    As[0][asub + 4][arow] = ra1.x; As[0][asub + 5][arow] = ra1.y;
    As[0][asub + 6][arow] = ra1.z; As[0][asub + 7][arow] = ra1.w;
    #pragma unroll
    for (int i = 0; i < 8; i++) Bs[0][bsub + i][bn] = rbv[i];
    __syncthreads();

    float acc[8][8];
    #pragma unroll
    for (int i = 0; i < 8; i++)
        #pragma unroll
        for (int j = 0; j < 8; j++) acc[i][j] = 0.0f;

    for (int tI = 0; tI < nT; tI++) {
        int  buf  = tI & 1;
        bool more = (tI + 1 < nT);

        if (more) {
            const float* apn = ap + (tI + 1) * BK;
            ra0 = *(const float4*)(apn);
            ra1 = *(const float4*)(apn + 4);
            const float* bpn = bp + (size_t)(tI + 1) * BK * NNP;
            #pragma unroll
            for (int i = 0; i < 8; i++) rbv[i] = bpn[(size_t)i * NNP];
        }

        #pragma unroll
        for (int kk = 0; kk < BK; kk++) {
            float a[8], bv[8];
            *(float4*)&a[0]  = *(const float4*)&As[buf][kk][tr];
            *(float4*)&a[4]  = *(const float4*)&As[buf][kk][tr + 4];
            *(float4*)&bv[0] = *(const float4*)&Bs[buf][kk][tc];
            *(float4*)&bv[4] = *(const float4*)&Bs[buf][kk][tc + 4];
            #pragma unroll
            for (int i = 0; i < 8; i++)
                #pragma unroll
                for (int j = 0; j < 8; j++)
                    acc[i][j] = __fmaf_rn(a[i], bv[j], acc[i][j]);
        }

        if (more) {
            int nb = buf ^ 1;
            As[nb][asub + 0][arow] = ra0.x; As[nb][asub + 1][arow] = ra0.y;
            As[nb][asub + 2][arow] = ra0.z; As[nb][asub + 3][arow] = ra0.w;
            As[nb][asub + 4][arow] = ra1.x; As[nb][asub + 5][arow] = ra1.y;
            As[nb][asub + 6][arow] = ra1.z; As[nb][asub + 7][arow] = ra1.w;
            #pragma unroll
            for (int i = 0; i < 8; i++) Bs[nb][bsub + i][bn] = rbv[i];
        }
        __syncthreads();
    }

    #pragma unroll
    for (int i = 0; i < 8; i++) {
        float* crow = C + (size_t)(row0 + tr + i) * NNP + (col0 + tc);
        *(float4*)(crow)     = *(float4*)&acc[i][0];
        *(float4*)(crow + 4) = *(float4*)&acc[i][4];
    }
}

// ---------------- phase 2: fused 100-step LIF, float4 lanes -------------------
// 512 threads. Thread tid owns n = 4*tid..4*tid+3 (vector, n<2048) and, for
// tid<20, scalar tail n = 2048+tid. Per-element fp order == reference:
//   ff=(p0+p1)+p2; rec = kc=320-panel fold of ascending active-row adds;
//   cur=fadd(ff,rec); mem=fadd(fmul(fmul(TAU,mem),fsub(1,spk)),cur); spk=mem>=1
#define NT    512
#define W4ROW 517            // 2068 / 4 float4s per W_rec row

__device__ __forceinline__ float4 f4add(float4 a, float4 b) {
    return make_float4(__fadd_rn(a.x, b.x), __fadd_rn(a.y, b.y),
                       __fadd_rn(a.z, b.z), __fadd_rn(a.w, b.w));
}

__global__ __launch_bounds__(NT, 2) void steps_kernel(const float* __restrict__ Wrec,
                                                      float* __restrict__ out) {
    __shared__ int s_list[NN];
    __shared__ int s_wcnt[16];
    __shared__ int s_tcnt;

    int b    = blockIdx.x;
    int tid  = threadIdx.x;
    int wid  = tid >> 5;
    int lane = tid & 31;
    unsigned ltmask = (1u << lane) - 1u;
    bool tv  = (tid < NOUT);

    const float4* W4 = (const float4*)Wrec;

    float4 mv = make_float4(0.f, 0.f, 0.f, 0.f);
    float4 sv = make_float4(0.f, 0.f, 0.f, 0.f);
    float  mt = 0.f, st = 0.f;

    const float* ff0 = g_ffp[0];
    const float* ff1 = g_ffp[1];
    const float* ff2 = g_ffp[2];

    for (int t = 0; t < T_; t++) {
        // ---- ff fold (independent, issued first): ff = (p0 + p1) + p2 ----
        size_t rbase  = ((size_t)t * B_ + b) * NNP;
        size_t rbase4 = rbase >> 2;
        float4 p0 = ((const float4*)ff0)[rbase4 + tid];
        float4 p1 = ((const float4*)ff1)[rbase4 + tid];
        float4 p2 = ((const float4*)ff2)[rbase4 + tid];
        float4 ffv = f4add(f4add(p0, p1), p2);
        float  fft = tv ? __fadd_rn(__fadd_rn(ff0[rbase + 2048 + tid],
                                              ff1[rbase + 2048 + tid]),
                                    ff2[rbase + 2048 + tid]) : 0.f;

        // ---- compaction: 4-bit mask + warp scan + cross-warp prefix ----
        unsigned am = (sv.x != 0.f ? 1u : 0u) | (sv.y != 0.f ? 2u : 0u)
                    | (sv.z != 0.f ? 4u : 0u) | (sv.w != 0.f ? 8u : 0u);
        int nact = __popc(am);
        int scan = nact;
        #pragma unroll
        for (int d = 1; d < 32; d <<= 1) {
            int o = __shfl_up_sync(0xffffffffu, scan, d);
            if (lane >= d) scan += o;
        }
        if (lane == 31) s_wcnt[wid] = scan;          // warp total

        bool ta = tv && (st != 0.f);
        unsigned tmask = __ballot_sync(0xffffffffu, ta);   // valid in warp 0
        if (tid == 0) s_tcnt = __popc(tmask);
        __syncthreads();

        int vbase = 0, vtotal = 0;
        #pragma unroll
        for (int w = 0; w < 16; w++) {
            int c = s_wcnt[w];
            if (w < wid) vbase += c;
            vtotal += c;
        }
        int pos = vbase + (scan - nact);             // exclusive within warp
        if (am & 1u) s_list[pos++] = 4 * tid + 0;
        if (am & 2u) s_list[pos++] = 4 * tid + 1;
        if (am & 4u) s_list[pos++] = 4 * tid + 2;
        if (am & 8u) s_list[pos++] = 4 * tid + 3;
        if (ta) s_list[vtotal + __popc(tmask & ltmask)] = 2048 + tid;
        __syncthreads();

        int cnt = vtotal + s_tcnt;

        // ---- rec: panel-folded ascending adds, unroll-4 float4 gather ----
        float4 rec  = make_float4(0.f, 0.f, 0.f, 0.f);
        float4 part = make_float4(0.f, 0.f, 0.f, 0.f);
        float  rect = 0.f, partt = 0.f;

        int curp = 0;
        int i = 0;
        for (; i + 4 <= cnt; i += 4) {
            int m0 = s_list[i + 0], m1 = s_list[i + 1];
            int m2 = s_list[i + 2], m3 = s_list[i + 3];
            float4 v0 = W4[(size_t)m0 * W4ROW + tid];
            float4 v1 = W4[(size_t)m1 * W4ROW + tid];
            float4 v2 = W4[(size_t)m2 * W4ROW + tid];
            float4 v3 = W4[(size_t)m3 * W4ROW + tid];
            float  t0 = tv ? Wrec[(size_t)m0 * NN + 2048 + tid] : 0.f;
            float  t1 = tv ? Wrec[(size_t)m1 * NN + 2048 + tid] : 0.f;
            float  t2 = tv ? Wrec[(size_t)m2 * NN + 2048 + tid] : 0.f;
            float  t3 = tv ? Wrec[(size_t)m3 * NN + 2048 + tid] : 0.f;
            int p;
            p = m0 / KC; if (p != curp) { rec = f4add(rec, part); rect = __fadd_rn(rect, partt);
                                          part = make_float4(0.f,0.f,0.f,0.f); partt = 0.f; curp = p; }
            part = f4add(part, v0); partt = __fadd_rn(partt, t0);
            p = m1 / KC; if (p != curp) { rec = f4add(rec, part); rect = __fadd_rn(rect, partt);
                                          part = make_float4(0.f,0.f,0.f,0.f); partt = 0.f; curp = p; }
            part = f4add(part, v1); partt = __fadd_rn(partt, t1);
            p = m2 / KC; if (p != curp) { rec = f4add(rec, part); rect = __fadd_rn(rect, partt);
                                          part = make_float4(0.f,0.f,0.f,0.f); partt = 0.f; curp = p; }
            part = f4add(part, v2); partt = __fadd_rn(partt, t2);
            p = m3 / KC; if (p != curp) { rec = f4add(rec, part); rect = __fadd_rn(rect, partt);
                                          part = make_float4(0.f,0.f,0.f,0.f); partt = 0.f; curp = p; }
            part = f4add(part, v3); partt = __fadd_rn(partt, t3);
        }
        for (; i < cnt; i++) {
            int mr = s_list[i];
            float4 v0 = W4[(size_t)mr * W4ROW + tid];
            float  t0 = tv ? Wrec[(size_t)mr * NN + 2048 + tid] : 0.f;
            int p = mr / KC;
            if (p != curp) { rec = f4add(rec, part); rect = __fadd_rn(rect, partt);
                             part = make_float4(0.f,0.f,0.f,0.f); partt = 0.f; curp = p; }
            part = f4add(part, v0); partt = __fadd_rn(partt, t0);
        }
        rec  = f4add(rec, part);
        rect = __fadd_rn(rect, partt);

        // ---- membrane update + spikes (unfused, reference order) ----
        {
            float4 cur = f4add(ffv, rec);
            float4 t1v = make_float4(__fmul_rn(TAU, mv.x), __fmul_rn(TAU, mv.y),
                                     __fmul_rn(TAU, mv.z), __fmul_rn(TAU, mv.w));
            float4 t2v = make_float4(__fsub_rn(1.f, sv.x), __fsub_rn(1.f, sv.y),
                                     __fsub_rn(1.f, sv.z), __fsub_rn(1.f, sv.w));
            mv = make_float4(__fadd_rn(__fmul_rn(t1v.x, t2v.x), cur.x),
                             __fadd_rn(__fmul_rn(t1v.y, t2v.y), cur.y),
                             __fadd_rn(__fmul_rn(t1v.z, t2v.z), cur.z),
                             __fadd_rn(__fmul_rn(t1v.w, t2v.w), cur.w));
            sv = make_float4(mv.x >= 1.f ? 1.f : 0.f, mv.y >= 1.f ? 1.f : 0.f,
                             mv.z >= 1.f ? 1.f : 0.f, mv.w >= 1.f ? 1.f : 0.f);
        }
        if (tv) {
            float cur = __fadd_rn(fft, rect);
            float t1  = __fmul_rn(TAU, mt);
            float t2  = __fsub_rn(1.f, st);
            mt = __fadd_rn(__fmul_rn(t1, t2), cur);
            st = (mt >= 1.f) ? 1.f : 0.f;
            out[((size_t)b * T_ + t) * NOUT + tid] = st;
        }

        __syncthreads();   // protect s_list/s_wcnt reuse next step
    }
}

// ---------------- launch -----------------------------------------------------
extern "C" void kernel_launch(void* const* d_in, const int* in_sizes, int n_in,
                              void* d_out, int out_size) {
    const float* x  = (const float*)d_in[0];   // [B, T, NIN]
    const float* W1 = (const float*)d_in[1];   // [NN, NIN]
    const float* Wr = (const float*)d_in[2];   // [NN, NN]
    float* out = (float*)d_out;                // [B, T, NOUT]

    {
        size_t n = (size_t)MROWS * KP;
        pad_x_kernel<<<(unsigned)((n + 255) / 256), 256>>>(x);
    }
    {
        size_t n = (size_t)KP * NNP;
        pad_w1t_kernel<<<(unsigned)((n + 255) / 256), 256>>>(W1);
    }

    dim3 ggrid(NNP / BN, MROWS / BM, 3);   // 17 x 200 x 3 slabs
    gemm_slab_kernel<<<ggrid, 256>>>();

    steps_kernel<<<B_, NT>>>(Wr, out);
}

// round 11
// speedup vs baseline: 1.3574x; 1.0308x over previous
#include <cuda_runtime.h>
#include <cstdint>

#define B_   256
#define T_   100
#define NIN  700
#define KP   704            // NIN padded to multiple of 16
#define NN   2068
#define NNP  2176           // NN padded to multiple of 64
#define NOUT 20
#define TAU  0.6f
#define KC   320            // Eigen kc panel size
#define NSEG 7              // ceil(2068/320)
#define MROWS (B_ * T_)     // 25600

// ---------------- scratch (device globals; no runtime allocation) ----------
__device__ float g_ff[(size_t)MROWS * NNP];      // folded ff = (p0+p1)+p2
__device__ float g_xp[(size_t)MROWS * KP];       // x staged: [r = t*B+b][k], zero-padded
__device__ float g_w1t[(size_t)KP * NNP];        // W_fc1^T zero-padded: [k][n]

// ---------------- staging ---------------------------------------------------
__global__ void pad_x_kernel(const float* __restrict__ x) {
    size_t idx = (size_t)blockIdx.x * blockDim.x + threadIdx.x;
    if (idx < (size_t)MROWS * KP) {
        int r = (int)(idx / KP);
        int k = (int)(idx - (size_t)r * KP);
        int t = r >> 8;                 // r = t*256 + b
        int b = r & 255;
        g_xp[idx] = (k < NIN) ? x[((size_t)b * T_ + t) * NIN + k] : 0.0f;
    }
}

__global__ void pad_w1t_kernel(const float* __restrict__ W1) {
    size_t idx = (size_t)blockIdx.x * blockDim.x + threadIdx.x;
    if (idx < (size_t)KP * NNP) {
        int k = (int)(idx / NNP);
        int n = (int)(idx - (size_t)k * NNP);
        g_w1t[idx] = (k < NIN && n < NN) ? W1[(size_t)n * NIN + k] : 0.0f;
    }
}

// ---------------- phase 1: GEMM with in-kernel panel fold --------------------
// Per output element (Eigen-exact): pac = seq-FMA over kc=320 panel;
// tot = fadd(tot, pac) at panel boundaries (k=320, 640) and at the end.
#define BM 128
#define BN 64
#define BK 16
#define NKT (KP / BK)       // 44 k-tiles; panel folds before tiles 20 and 40

__global__ __launch_bounds__(256, 2) void gemm_fold_kernel() {
    __shared__ float As[2][BK][BM];
    __shared__ float Bs[2][BK][BN];

    int tid  = threadIdx.x;
    int row0 = blockIdx.y * BM;
    int col0 = blockIdx.x * BN;

    int arow = tid >> 1;
    int asub = (tid & 1) * 8;
    const float* ap = g_xp + (size_t)(row0 + arow) * KP + asub;

    int bk  = tid >> 4;           // 0..15
    int bn4 = (tid & 15) * 4;     // 0..60
    const float* bp = g_w1t + (size_t)bk * NNP + (col0 + bn4);

    int tr = (tid >> 4) * 8;
    int tc = (tid & 15) * 4;

    float4 ra0, ra1, rb;

    // prolog: tile 0
    ra0 = *(const float4*)(ap);
    ra1 = *(const float4*)(ap + 4);
    rb  = *(const float4*)(bp);

    As[0][asub + 0][arow] = ra0.x; As[0][asub + 1][arow] = ra0.y;
    As[0][asub + 2][arow] = ra0.z; As[0][asub + 3][arow] = ra0.w;
    As[0][asub + 4][arow] = ra1.x; As[0][asub + 5][arow] = ra1.y;
    As[0][asub + 6][arow] = ra1.z; As[0][asub + 7][arow] = ra1.w;
    *(float4*)&Bs[0][bk][bn4] = rb;
    __syncthreads();

    float tot[8][4], pac[8][4];
    #pragma unroll
    for (int i = 0; i < 8; i++)
        #pragma unroll
        for (int j = 0; j < 4; j++) { tot[i][j] = 0.0f; pac[i][j] = 0.0f; }

    for (int tI = 0; tI < NKT; tI++) {
        if (tI == 20 || tI == 40) {                 // panel boundary fold
            #pragma unroll
            for (int i = 0; i < 8; i++)
                #pragma unroll
                for (int j = 0; j < 4; j++) {
                    tot[i][j] = __fadd_rn(tot[i][j], pac[i][j]);
                    pac[i][j] = 0.0f;
                }
        }

        int  buf  = tI & 1;
        bool more = (tI + 1 < NKT);

        if (more) {
            const float* apn = ap + (tI + 1) * BK;
            ra0 = *(const float4*)(apn);
            ra1 = *(const float4*)(apn + 4);
            rb  = *(const float4*)(bp + (size_t)(tI + 1) * BK * NNP);
        }

        #pragma unroll
        for (int kk = 0; kk < BK; kk++) {
            float a[8], bv[4];
            *(float4*)&a[0]  = *(const float4*)&As[buf][kk][tr];
            *(float4*)&a[4]  = *(const float4*)&As[buf][kk][tr + 4];
            *(float4*)&bv[0] = *(const float4*)&Bs[buf][kk][tc];
            #pragma unroll
            for (int i = 0; i < 8; i++)
                #pragma unroll
                for (int j = 0; j < 4; j++)
                    pac[i][j] = __fmaf_rn(a[i], bv[j], pac[i][j]);
        }

        if (more) {
            int nb = buf ^ 1;
            As[nb][asub + 0][arow] = ra0.x; As[nb][asub + 1][arow] = ra0.y;
            As[nb][asub + 2][arow] = ra0.z; As[nb][asub + 3][arow] = ra0.w;
            As[nb][asub + 4][arow] = ra1.x; As[nb][asub + 5][arow] = ra1.y;
            As[nb][asub + 6][arow] = ra1.z; As[nb][asub + 7][arow] = ra1.w;
            *(float4*)&Bs[nb][bk][bn4] = rb;
        }
        __syncthreads();
    }

    #pragma unroll
    for (int i = 0; i < 8; i++) {
        #pragma unroll
        for (int j = 0; j < 4; j++)
            tot[i][j] = __fadd_rn(tot[i][j], pac[i][j]);   // final panel fold
        *(float4*)(g_ff + (size_t)(row0 + tr + i) * NNP + (col0 + tc)) = *(float4*)&tot[i][0];
    }
}

// ---------------- phase 2: fused 100-step LIF, segmented float4 gather -------
// 512 threads. Thread tid owns n = 4*tid..4*tid+3 (vector) and, for tid<20,
// scalar tail n = 2048+tid. Ascending active list; panel folds via 7 segment
// boundaries found by binary search (empty segments fold +0 => bitwise no-op).
#define NT    512
#define W4ROW 517            // 2068 / 4 float4s per W_rec row

__device__ __forceinline__ float4 f4add(float4 a, float4 b) {
    return make_float4(__fadd_rn(a.x, b.x), __fadd_rn(a.y, b.y),
                       __fadd_rn(a.z, b.z), __fadd_rn(a.w, b.w));
}

__global__ __launch_bounds__(NT, 2) void steps_kernel(const float* __restrict__ Wrec,
                                                      float* __restrict__ out) {
    __shared__ int s_list[NN];
    __shared__ int s_wcnt[16];
    __shared__ int s_tcnt;
    __shared__ int s_seg[NSEG];

    int b    = blockIdx.x;
    int tid  = threadIdx.x;
    int wid  = tid >> 5;
    int lane = tid & 31;
    unsigned ltmask = (1u << lane) - 1u;
    bool tv  = (tid < NOUT);

    const float4* W4 = (const float4*)Wrec;

    float4 mv = make_float4(0.f, 0.f, 0.f, 0.f);
    float4 sv = make_float4(0.f, 0.f, 0.f, 0.f);
    float  mt = 0.f, st = 0.f;

    for (int t = 0; t < T_; t++) {
        // ---- ff load (already panel-folded by GEMM) ----
        size_t rbase = ((size_t)t * B_ + b) * NNP;
        float4 ffv = ((const float4*)g_ff)[(rbase >> 2) + tid];
        float  fft = tv ? g_ff[rbase + 2048 + tid] : 0.f;

        // ---- compaction: 4-bit mask + warp scan + cross-warp prefix ----
        unsigned am = (sv.x != 0.f ? 1u : 0u) | (sv.y != 0.f ? 2u : 0u)
                    | (sv.z != 0.f ? 4u : 0u) | (sv.w != 0.f ? 8u : 0u);
        int nact = __popc(am);
        int scan = nact;
        #pragma unroll
        for (int d = 1; d < 32; d <<= 1) {
            int o = __shfl_up_sync(0xffffffffu, scan, d);
            if (lane >= d) scan += o;
        }
        if (lane == 31) s_wcnt[wid] = scan;

        bool ta = tv && (st != 0.f);
        unsigned tmask = __ballot_sync(0xffffffffu, ta);   // valid in warp 0
        if (tid == 0) s_tcnt = __popc(tmask);
        __syncthreads();

        int vbase = 0, vtotal = 0;
        #pragma unroll
        for (int w = 0; w < 16; w++) {
            int c = s_wcnt[w];
            if (w < wid) vbase += c;
            vtotal += c;
        }
        int pos = vbase + (scan - nact);
        if (am & 1u) s_list[pos++] = 4 * tid + 0;
        if (am & 2u) s_list[pos++] = 4 * tid + 1;
        if (am & 4u) s_list[pos++] = 4 * tid + 2;
        if (am & 8u) s_list[pos++] = 4 * tid + 3;
        if (ta) s_list[vtotal + __popc(tmask & ltmask)] = 2048 + tid;
        __syncthreads();

        int cnt = vtotal + s_tcnt;

        // ---- segment boundaries: lower_bound of (p+1)*320 in s_list ----
        if (tid < NSEG) {
            int target = (tid + 1) * KC;
            int lo = 0, hi = cnt;
            while (lo < hi) {
                int mid = (lo + hi) >> 1;
                if (s_list[mid] < target) lo = mid + 1; else hi = mid;
            }
            s_seg[tid] = lo;    // s_seg[6] == cnt (target 2240 > max m)
        }
        __syncthreads();

        // ---- rec: per-segment plain adds, fold between segments ----
        float4 rec  = make_float4(0.f, 0.f, 0.f, 0.f);
        float  rect = 0.f;

        int start = 0;
        #pragma unroll 1
        for (int p = 0; p < NSEG; p++) {
            int end = s_seg[p];
            float4 part = make_float4(0.f, 0.f, 0.f, 0.f);
            float  partt = 0.f;
            int i = start;
            for (; i + 4 <= end; i += 4) {
                int m0 = s_list[i + 0], m1 = s_list[i + 1];
                int m2 = s_list[i + 2], m3 = s_list[i + 3];
                float4 v0 = W4[(size_t)m0 * W4ROW + tid];
                float4 v1 = W4[(size_t)m1 * W4ROW + tid];
                float4 v2 = W4[(size_t)m2 * W4ROW + tid];
                float4 v3 = W4[(size_t)m3 * W4ROW + tid];
                float  t0 = tv ? Wrec[(size_t)m0 * NN + 2048 + tid] : 0.f;
                float  t1 = tv ? Wrec[(size_t)m1 * NN + 2048 + tid] : 0.f;
                float  t2 = tv ? Wrec[(size_t)m2 * NN + 2048 + tid] : 0.f;
                float  t3 = tv ? Wrec[(size_t)m3 * NN + 2048 + tid] : 0.f;
                part = f4add(part, v0); partt = __fadd_rn(partt, t0);
                part = f4add(part, v1); partt = __fadd_rn(partt, t1);
                part = f4add(part, v2); partt = __fadd_rn(partt, t2);
                part = f4add(part, v3); partt = __fadd_rn(partt, t3);
            }
            for (; i < end; i++) {
                int mr = s_list[i];
                float4 v0 = W4[(size_t)mr * W4ROW + tid];
                float  t0 = tv ? Wrec[(size_t)mr * NN + 2048 + tid] : 0.f;
                part = f4add(part, v0); partt = __fadd_rn(partt, t0);
            }
            rec  = f4add(rec, part);            // fadd(x,+0) == x for empty segs
            rect = __fadd_rn(rect, partt);
            start = end;
        }

        // ---- membrane update + spikes (unfused, reference order) ----
        {
            float4 cur = f4add(ffv, rec);
            mv = make_float4(
                __fadd_rn(__fmul_rn(__fmul_rn(TAU, mv.x), __fsub_rn(1.f, sv.x)), cur.x),
                __fadd_rn(__fmul_rn(__fmul_rn(TAU, mv.y), __fsub_rn(1.f, sv.y)), cur.y),
                __fadd_rn(__fmul_rn(__fmul_rn(TAU, mv.z), __fsub_rn(1.f, sv.z)), cur.z),
                __fadd_rn(__fmul_rn(__fmul_rn(TAU, mv.w), __fsub_rn(1.f, sv.w)), cur.w));
            sv = make_float4(mv.x >= 1.f ? 1.f : 0.f, mv.y >= 1.f ? 1.f : 0.f,
                             mv.z >= 1.f ? 1.f : 0.f, mv.w >= 1.f ? 1.f : 0.f);
        }
        if (tv) {
            float cur = __fadd_rn(fft, rect);
            mt = __fadd_rn(__fmul_rn(__fmul_rn(TAU, mt), __fsub_rn(1.f, st)), cur);
            st = (mt >= 1.f) ? 1.f : 0.f;
            out[((size_t)b * T_ + t) * NOUT + tid] = st;
        }

        __syncthreads();   // protect s_list/s_wcnt/s_seg reuse next step
    }
}

// ---------------- launch -----------------------------------------------------
extern "C" void kernel_launch(void* const* d_in, const int* in_sizes, int n_in,
                              void* d_out, int out_size) {
    const float* x  = (const float*)d_in[0];   // [B, T, NIN]
    const float* W1 = (const float*)d_in[1];   // [NN, NIN]
    const float* Wr = (const float*)d_in[2];   // [NN, NN]
    float* out = (float*)d_out;                // [B, T, NOUT]

    {
        size_t n = (size_t)MROWS * KP;
        pad_x_kernel<<<(unsigned)((n + 255) / 256), 256>>>(x);
    }
    {
        size_t n = (size_t)KP * NNP;
        pad_w1t_kernel<<<(unsigned)((n + 255) / 256), 256>>>(W1);
    }

    dim3 ggrid(NNP / BN, MROWS / BM);   // 34 x 200
    gemm_fold_kernel<<<ggrid, 256>>>();

    steps_kernel<<<B_, NT>>>(Wr, out);
}

// round 12
// speedup vs baseline: 1.4899x; 1.0976x over previous
#include <cuda_runtime.h>
#include <cstdint>

#define B_   256
#define T_   100
#define NIN  700
#define KP   704            // NIN padded to multiple of 16
#define NN   2068
#define NNP  2176           // NN padded to multiple of 64
#define NOUT 20
#define TAU  0.6f
#define KC   320            // Eigen kc panel size
#define NSEG 7              // ceil(2068/320)
#define MROWS (B_ * T_)     // 25600

#define CH   10             // timesteps per chunk
#define NCH  (T_ / CH)      // 10 chunks
#define RPC  (B_ * CH)      // 2560 rows per chunk

// ---------------- scratch (device globals; no runtime allocation) ----------
__device__ float g_ff[(size_t)MROWS * NNP];      // folded ff = (p0+p1)+p2
__device__ float g_xp[(size_t)MROWS * KP];       // x staged: [r = t*B+b][k], zero-padded
__device__ float g_w1t[(size_t)KP * NNP];        // W_fc1^T zero-padded: [k][n]
__device__ float g_mem[(size_t)B_ * NNP];        // inter-chunk membrane state
__device__ float g_spk[(size_t)B_ * NNP];        // inter-chunk spike state

// ---------------- streams/events (created once at load; no device memory) ---
struct GpuCtx {
    cudaStream_t sG;
    cudaEvent_t  evStage;
    cudaEvent_t  evG[NCH];
    GpuCtx() {
        cudaStreamCreateWithFlags(&sG, cudaStreamNonBlocking);
        cudaEventCreateWithFlags(&evStage, cudaEventDisableTiming);
        for (int i = 0; i < NCH; i++)
            cudaEventCreateWithFlags(&evG[i], cudaEventDisableTiming);
    }
};
static GpuCtx g_ctx;

// ---------------- staging ---------------------------------------------------
__global__ void pad_x_kernel(const float* __restrict__ x) {
    size_t idx = (size_t)blockIdx.x * blockDim.x + threadIdx.x;
    if (idx < (size_t)MROWS * KP) {
        int r = (int)(idx / KP);
        int k = (int)(idx - (size_t)r * KP);
        int t = r >> 8;                 // r = t*256 + b
        int b = r & 255;
        g_xp[idx] = (k < NIN) ? x[((size_t)b * T_ + t) * NIN + k] : 0.0f;
    }
}

__global__ void pad_w1t_kernel(const float* __restrict__ W1) {
    size_t idx = (size_t)blockIdx.x * blockDim.x + threadIdx.x;
    if (idx < (size_t)KP * NNP) {
        int k = (int)(idx / NNP);
        int n = (int)(idx - (size_t)k * NNP);
        g_w1t[idx] = (k < NIN && n < NN) ? W1[(size_t)n * NIN + k] : 0.0f;
    }
}

// ---------------- phase 1: GEMM with in-kernel panel fold (chunked rows) -----
// Per output element (Eigen-exact): pac = seq-FMA over kc=320 panel;
// tot = fadd(tot, pac) at panel boundaries (k=320, 640) and at the end.
#define BM 128
#define BN 64
#define BK 16
#define NKT (KP / BK)       // 44 k-tiles; panel folds before tiles 20 and 40

__global__ __launch_bounds__(256, 2) void gemm_fold_kernel(int row_off) {
    __shared__ float As[2][BK][BM];
    __shared__ float Bs[2][BK][BN];

    int tid  = threadIdx.x;
    int row0 = row_off + blockIdx.y * BM;
    int col0 = blockIdx.x * BN;

    int arow = tid >> 1;
    int asub = (tid & 1) * 8;
    const float* ap = g_xp + (size_t)(row0 + arow) * KP + asub;

    int bk  = tid >> 4;           // 0..15
    int bn4 = (tid & 15) * 4;     // 0..60
    const float* bp = g_w1t + (size_t)bk * NNP + (col0 + bn4);

    int tr = (tid >> 4) * 8;
    int tc = (tid & 15) * 4;

    float4 ra0, ra1, rb;

    ra0 = *(const float4*)(ap);
    ra1 = *(const float4*)(ap + 4);
    rb  = *(const float4*)(bp);

    As[0][asub + 0][arow] = ra0.x; As[0][asub + 1][arow] = ra0.y;
    As[0][asub + 2][arow] = ra0.z; As[0][asub + 3][arow] = ra0.w;
    As[0][asub + 4][arow] = ra1.x; As[0][asub + 5][arow] = ra1.y;
    As[0][asub + 6][arow] = ra1.z; As[0][asub + 7][arow] = ra1.w;
    *(float4*)&Bs[0][bk][bn4] = rb;
    __syncthreads();

    float tot[8][4], pac[8][4];
    #pragma unroll
    for (int i = 0; i < 8; i++)
        #pragma unroll
        for (int j = 0; j < 4; j++) { tot[i][j] = 0.0f; pac[i][j] = 0.0f; }

    for (int tI = 0; tI < NKT; tI++) {
        if (tI == 20 || tI == 40) {                 // panel boundary fold
            #pragma unroll
            for (int i = 0; i < 8; i++)
                #pragma unroll
                for (int j = 0; j < 4; j++) {
                    tot[i][j] = __fadd_rn(tot[i][j], pac[i][j]);
                    pac[i][j] = 0.0f;
                }
        }

        int  buf  = tI & 1;
        bool more = (tI + 1 < NKT);

        if (more) {
            const float* apn = ap + (tI + 1) * BK;
            ra0 = *(const float4*)(apn);
            ra1 = *(const float4*)(apn + 4);
            rb  = *(const float4*)(bp + (size_t)(tI + 1) * BK * NNP);
        }

        #pragma unroll
        for (int kk = 0; kk < BK; kk++) {
            float a[8], bv[4];
            *(float4*)&a[0]  = *(const float4*)&As[buf][kk][tr];
            *(float4*)&a[4]  = *(const float4*)&As[buf][kk][tr + 4];
            *(float4*)&bv[0] = *(const float4*)&Bs[buf][kk][tc];
            #pragma unroll
            for (int i = 0; i < 8; i++)
                #pragma unroll
                for (int j = 0; j < 4; j++)
                    pac[i][j] = __fmaf_rn(a[i], bv[j], pac[i][j]);
        }

        if (more) {
            int nb = buf ^ 1;
            As[nb][asub + 0][arow] = ra0.x; As[nb][asub + 1][arow] = ra0.y;
            As[nb][asub + 2][arow] = ra0.z; As[nb][asub + 3][arow] = ra0.w;
            As[nb][asub + 4][arow] = ra1.x; As[nb][asub + 5][arow] = ra1.y;
            As[nb][asub + 6][arow] = ra1.z; As[nb][asub + 7][arow] = ra1.w;
            *(float4*)&Bs[nb][bk][bn4] = rb;
        }
        __syncthreads();
    }

    #pragma unroll
    for (int i = 0; i < 8; i++) {
        #pragma unroll
        for (int j = 0; j < 4; j++)
            tot[i][j] = __fadd_rn(tot[i][j], pac[i][j]);   // final panel fold
        *(float4*)(g_ff + (size_t)(row0 + tr + i) * NNP + (col0 + tc)) = *(float4*)&tot[i][0];
    }
}

// ---------------- phase 2: CH-step LIF chunk, segmented float4 gather --------
#define NT    512
#define W4ROW 517            // 2068 / 4 float4s per W_rec row

__device__ __forceinline__ float4 f4add(float4 a, float4 b) {
    return make_float4(__fadd_rn(a.x, b.x), __fadd_rn(a.y, b.y),
                       __fadd_rn(a.z, b.z), __fadd_rn(a.w, b.w));
}

__global__ __launch_bounds__(NT, 2) void steps_kernel(const float* __restrict__ Wrec,
                                                      float* __restrict__ out, int t0) {
    __shared__ int s_list[NN];
    __shared__ int s_wcnt[16];
    __shared__ int s_tcnt;
    __shared__ int s_seg[NSEG];

    int b    = blockIdx.x;
    int tid  = threadIdx.x;
    int wid  = tid >> 5;
    int lane = tid & 31;
    unsigned ltmask = (1u << lane) - 1u;
    bool tv  = (tid < NOUT);

    const float4* W4 = (const float4*)Wrec;
    size_t sb  = (size_t)b * NNP;
    size_t sb4 = sb >> 2;

    float4 mv, sv;
    float  mt, st;
    if (t0 == 0) {
        mv = make_float4(0.f, 0.f, 0.f, 0.f);
        sv = make_float4(0.f, 0.f, 0.f, 0.f);
        mt = 0.f; st = 0.f;
    } else {
        mv = ((const float4*)g_mem)[sb4 + tid];
        sv = ((const float4*)g_spk)[sb4 + tid];
        mt = tv ? g_mem[sb + 2048 + tid] : 0.f;
        st = tv ? g_spk[sb + 2048 + tid] : 0.f;
    }

    for (int t = t0; t < t0 + CH; t++) {
        // ---- ff load (already panel-folded by GEMM) ----
        size_t rbase = ((size_t)t * B_ + b) * NNP;
        float4 ffv = ((const float4*)g_ff)[(rbase >> 2) + tid];
        float  fft = tv ? g_ff[rbase + 2048 + tid] : 0.f;

        // ---- compaction: 4-bit mask + warp scan + cross-warp prefix ----
        unsigned am = (sv.x != 0.f ? 1u : 0u) | (sv.y != 0.f ? 2u : 0u)
                    | (sv.z != 0.f ? 4u : 0u) | (sv.w != 0.f ? 8u : 0u);
        int nact = __popc(am);
        int scan = nact;
        #pragma unroll
        for (int d = 1; d < 32; d <<= 1) {
            int o = __shfl_up_sync(0xffffffffu, scan, d);
            if (lane >= d) scan += o;
        }
        if (lane == 31) s_wcnt[wid] = scan;

        bool ta = tv && (st != 0.f);
        unsigned tmask = __ballot_sync(0xffffffffu, ta);   // valid in warp 0
        if (tid == 0) s_tcnt = __popc(tmask);
        __syncthreads();

        int vbase = 0, vtotal = 0;
        #pragma unroll
        for (int w = 0; w < 16; w++) {
            int c = s_wcnt[w];
            if (w < wid) vbase += c;
            vtotal += c;
        }
        int pos = vbase + (scan - nact);
        if (am & 1u) s_list[pos++] = 4 * tid + 0;
        if (am & 2u) s_list[pos++] = 4 * tid + 1;
        if (am & 4u) s_list[pos++] = 4 * tid + 2;
        if (am & 8u) s_list[pos++] = 4 * tid + 3;
        if (ta) s_list[vtotal + __popc(tmask & ltmask)] = 2048 + tid;
        __syncthreads();

        int cnt = vtotal + s_tcnt;

        // ---- segment boundaries: lower_bound of (p+1)*320 in s_list ----
        if (tid < NSEG) {
            int target = (tid + 1) * KC;
            int lo = 0, hi = cnt;
            while (lo < hi) {
                int mid = (lo + hi) >> 1;
                if (s_list[mid] < target) lo = mid + 1; else hi = mid;
            }
            s_seg[tid] = lo;
        }
        __syncthreads();

        // ---- rec: per-segment plain adds, fold between segments ----
        float4 rec  = make_float4(0.f, 0.f, 0.f, 0.f);
        float  rect = 0.f;

        int start = 0;
        #pragma unroll 1
        for (int p = 0; p < NSEG; p++) {
            int end = s_seg[p];
            float4 part = make_float4(0.f, 0.f, 0.f, 0.f);
            float  partt = 0.f;
            int i = start;
            for (; i + 4 <= end; i += 4) {
                int m0 = s_list[i + 0], m1 = s_list[i + 1];
                int m2 = s_list[i + 2], m3 = s_list[i + 3];
                float4 v0 = W4[(size_t)m0 * W4ROW + tid];
                float4 v1 = W4[(size_t)m1 * W4ROW + tid];
                float4 v2 = W4[(size_t)m2 * W4ROW + tid];
                float4 v3 = W4[(size_t)m3 * W4ROW + tid];
                float  t0s = tv ? Wrec[(size_t)m0 * NN + 2048 + tid] : 0.f;
                float  t1s = tv ? Wrec[(size_t)m1 * NN + 2048 + tid] : 0.f;
                float  t2s = tv ? Wrec[(size_t)m2 * NN + 2048 + tid] : 0.f;
                float  t3s = tv ? Wrec[(size_t)m3 * NN + 2048 + tid] : 0.f;
                part = f4add(part, v0); partt = __fadd_rn(partt, t0s);
                part = f4add(part, v1); partt = __fadd_rn(partt, t1s);
                part = f4add(part, v2); partt = __fadd_rn(partt, t2s);
                part = f4add(part, v3); partt = __fadd_rn(partt, t3s);
            }
            for (; i < end; i++) {
                int mr = s_list[i];
                float4 v0 = W4[(size_t)mr * W4ROW + tid];
                float  t0s = tv ? Wrec[(size_t)mr * NN + 2048 + tid] : 0.f;
                part = f4add(part, v0); partt = __fadd_rn(partt, t0s);
            }
            rec  = f4add(rec, part);            // fadd(x,+0) == x for empty segs
            rect = __fadd_rn(rect, partt);
            start = end;
        }

        // ---- membrane update + spikes (unfused, reference order) ----
        {
            float4 cur = f4add(ffv, rec);
            mv = make_float4(
                __fadd_rn(__fmul_rn(__fmul_rn(TAU, mv.x), __fsub_rn(1.f, sv.x)), cur.x),
                __fadd_rn(__fmul_rn(__fmul_rn(TAU, mv.y), __fsub_rn(1.f, sv.y)), cur.y),
                __fadd_rn(__fmul_rn(__fmul_rn(TAU, mv.z), __fsub_rn(1.f, sv.z)), cur.z),
                __fadd_rn(__fmul_rn(__fmul_rn(TAU, mv.w), __fsub_rn(1.f, sv.w)), cur.w));
            sv = make_float4(mv.x >= 1.f ? 1.f : 0.f, mv.y >= 1.f ? 1.f : 0.f,
                             mv.z >= 1.f ? 1.f : 0.f, mv.w >= 1.f ? 1.f : 0.f);
        }
        if (tv) {
            float cur = __fadd_rn(fft, rect);
            mt = __fadd_rn(__fmul_rn(__fmul_rn(TAU, mt), __fsub_rn(1.f, st)), cur);
            st = (mt >= 1.f) ? 1.f : 0.f;
            out[((size_t)b * T_ + t) * NOUT + tid] = st;
        }

        __syncthreads();   // protect s_list/s_wcnt/s_seg reuse next step
    }

    // ---- park state for next chunk ----
    ((float4*)g_mem)[sb4 + tid] = mv;
    ((float4*)g_spk)[sb4 + tid] = sv;
    if (tv) {
        g_mem[sb + 2048 + tid] = mt;
        g_spk[sb + 2048 + tid] = st;
    }
}

// ---------------- launch: stream-forked chunk pipeline ------------------------
extern "C" void kernel_launch(void* const* d_in, const int* in_sizes, int n_in,
                              void* d_out, int out_size) {
    const float* x  = (const float*)d_in[0];   // [B, T, NIN]
    const float* W1 = (const float*)d_in[1];   // [NN, NIN]
    const float* Wr = (const float*)d_in[2];   // [NN, NN]
    float* out = (float*)d_out;                // [B, T, NOUT]

    // staging on origin stream
    {
        size_t n = (size_t)MROWS * KP;
        pad_x_kernel<<<(unsigned)((n + 255) / 256), 256>>>(x);
    }
    {
        size_t n = (size_t)KP * NNP;
        pad_w1t_kernel<<<(unsigned)((n + 255) / 256), 256>>>(W1);
    }
    cudaEventRecord(g_ctx.evStage, 0);

    // GEMM chunks on forked stream sG
    cudaStreamWaitEvent(g_ctx.sG, g_ctx.evStage, 0);
    dim3 ggrid(NNP / BN, RPC / BM);            // 34 x 20 per chunk
    for (int c = 0; c < NCH; c++) {
        gemm_fold_kernel<<<ggrid, 256, 0, g_ctx.sG>>>(c * RPC);
        cudaEventRecord(g_ctx.evG[c], g_ctx.sG);
    }

    // steps chunks on origin stream, each gated on its GEMM chunk
    for (int c = 0; c < NCH; c++) {
        cudaStreamWaitEvent(0, g_ctx.evG[c], 0);
        steps_kernel<<<B_, NT>>>(Wr, out, c * CH);
    }
}

// round 13
// speedup vs baseline: 1.5077x; 1.0120x over previous
#include <cuda_runtime.h>
#include <cstdint>

#define B_   256
#define T_   100
#define NIN  700
#define KP   704            // NIN padded to multiple of 16
#define NN   2068
#define NNP  2176           // row stride (multiple of 64)
#define NCOLB 33            // col blocks actually computed (cols 0..2111 >= NN)
#define NOUT 20
#define TAU  0.6f
#define KC   320            // Eigen kc panel size
#define NSEG 7              // ceil(2068/320)
#define MROWS (B_ * T_)     // 25600

#define CH   10             // timesteps per chunk
#define NCH  (T_ / CH)      // 10 chunks
#define RPC  (B_ * CH)      // 2560 rows per chunk

// ---------------- scratch (device globals; no runtime allocation) ----------
__device__ float g_ff[(size_t)MROWS * NNP];      // folded ff = (p0+p1)+p2
__device__ float g_xp[(size_t)MROWS * KP];       // x staged: [r = t*B+b][k], zero-padded
__device__ float g_w1t[(size_t)KP * NNP];        // W_fc1^T zero-padded: [k][n]
__device__ float g_mem[(size_t)B_ * NNP];        // inter-chunk membrane state
__device__ float g_spk[(size_t)B_ * NNP];        // inter-chunk spike state

// ---------------- streams/events (created once at load; no device memory) ---
struct GpuCtx {
    cudaStream_t sG;            // low priority: GEMM
    cudaStream_t sS;            // high priority: steps
    cudaEvent_t  evStage;
    cudaEvent_t  evG[NCH];
    cudaEvent_t  evJoin;
    GpuCtx() {
        int lo, hi;
        cudaDeviceGetStreamPriorityRange(&lo, &hi);   // lo = least, hi = greatest
        cudaStreamCreateWithPriority(&sG, cudaStreamNonBlocking, lo);
        cudaStreamCreateWithPriority(&sS, cudaStreamNonBlocking, hi);
        cudaEventCreateWithFlags(&evStage, cudaEventDisableTiming);
        for (int i = 0; i < NCH; i++)
            cudaEventCreateWithFlags(&evG[i], cudaEventDisableTiming);
        cudaEventCreateWithFlags(&evJoin, cudaEventDisableTiming);
    }
};
static GpuCtx g_ctx;

// ---------------- staging ---------------------------------------------------
__global__ void pad_x_kernel(const float* __restrict__ x) {
    size_t idx = (size_t)blockIdx.x * blockDim.x + threadIdx.x;
    if (idx < (size_t)MROWS * KP) {
        int r = (int)(idx / KP);
        int k = (int)(idx - (size_t)r * KP);
        int t = r >> 8;                 // r = t*256 + b
        int b = r & 255;
        g_xp[idx] = (k < NIN) ? x[((size_t)b * T_ + t) * NIN + k] : 0.0f;
    }
}

__global__ void pad_w1t_kernel(const float* __restrict__ W1) {
    size_t idx = (size_t)blockIdx.x * blockDim.x + threadIdx.x;
    if (idx < (size_t)KP * NNP) {
        int k = (int)(idx / NNP);
        int n = (int)(idx - (size_t)k * NNP);
        g_w1t[idx] = (k < NIN && n < NN) ? W1[(size_t)n * NIN + k] : 0.0f;
    }
}

// ---------------- phase 1: GEMM with in-kernel panel fold (chunked rows) -----
// Per output element (Eigen-exact): pac = seq-FMA over kc=320 panel;
// tot = fadd(tot, pac) at panel boundaries (k=320, 640) and at the end.
#define BM 128
#define BN 64
#define BK 16
#define NKT (KP / BK)       // 44 k-tiles; panel folds before tiles 20 and 40

__global__ __launch_bounds__(256, 2) void gemm_fold_kernel(int row_off) {
    __shared__ float As[2][BK][BM];
    __shared__ float Bs[2][BK][BN];

    int tid  = threadIdx.x;
    int row0 = row_off + blockIdx.y * BM;
    int col0 = blockIdx.x * BN;

    int arow = tid >> 1;
    int asub = (tid & 1) * 8;
    const float* ap = g_xp + (size_t)(row0 + arow) * KP + asub;

    int bk  = tid >> 4;           // 0..15
    int bn4 = (tid & 15) * 4;     // 0..60
    const float* bp = g_w1t + (size_t)bk * NNP + (col0 + bn4);

    int tr = (tid >> 4) * 8;
    int tc = (tid & 15) * 4;

    float4 ra0, ra1, rb;

    ra0 = *(const float4*)(ap);
    ra1 = *(const float4*)(ap + 4);
    rb  = *(const float4*)(bp);

    As[0][asub + 0][arow] = ra0.x; As[0][asub + 1][arow] = ra0.y;
    As[0][asub + 2][arow] = ra0.z; As[0][asub + 3][arow] = ra0.w;
    As[0][asub + 4][arow] = ra1.x; As[0][asub + 5][arow] = ra1.y;
    As[0][asub + 6][arow] = ra1.z; As[0][asub + 7][arow] = ra1.w;
    *(float4*)&Bs[0][bk][bn4] = rb;
    __syncthreads();

    float tot[8][4], pac[8][4];
    #pragma unroll
    for (int i = 0; i < 8; i++)
        #pragma unroll
        for (int j = 0; j < 4; j++) { tot[i][j] = 0.0f; pac[i][j] = 0.0f; }

    for (int tI = 0; tI < NKT; tI++) {
        if (tI == 20 || tI == 40) {                 // panel boundary fold
            #pragma unroll
            for (int i = 0; i < 8; i++)
                #pragma unroll
                for (int j = 0; j < 4; j++) {
                    tot[i][j] = __fadd_rn(tot[i][j], pac[i][j]);
                    pac[i][j] = 0.0f;
                }
        }

        int  buf  = tI & 1;
        bool more = (tI + 1 < NKT);

        if (more) {
            const float* apn = ap + (tI + 1) * BK;
            ra0 = *(const float4*)(apn);
            ra1 = *(const float4*)(apn + 4);
            rb  = *(const float4*)(bp + (size_t)(tI + 1) * BK * NNP);
        }

        #pragma unroll
        for (int kk = 0; kk < BK; kk++) {
            float a[8], bv[4];
            *(float4*)&a[0]  = *(const float4*)&As[buf][kk][tr];
            *(float4*)&a[4]  = *(const float4*)&As[buf][kk][tr + 4];
            *(float4*)&bv[0] = *(const float4*)&Bs[buf][kk][tc];
            #pragma unroll
            for (int i = 0; i < 8; i++)
                #pragma unroll
                for (int j = 0; j < 4; j++)
                    pac[i][j] = __fmaf_rn(a[i], bv[j], pac[i][j]);
        }

        if (more) {
            int nb = buf ^ 1;
            As[nb][asub + 0][arow] = ra0.x; As[nb][asub + 1][arow] = ra0.y;
            As[nb][asub + 2][arow] = ra0.z; As[nb][asub + 3][arow] = ra0.w;
            As[nb][asub + 4][arow] = ra1.x; As[nb][asub + 5][arow] = ra1.y;
            As[nb][asub + 6][arow] = ra1.z; As[nb][asub + 7][arow] = ra1.w;
            *(float4*)&Bs[nb][bk][bn4] = rb;
        }
        __syncthreads();
    }

    #pragma unroll
    for (int i = 0; i < 8; i++) {
        #pragma unroll
        for (int j = 0; j < 4; j++)
            tot[i][j] = __fadd_rn(tot[i][j], pac[i][j]);   // final panel fold
        *(float4*)(g_ff + (size_t)(row0 + tr + i) * NNP + (col0 + tc)) = *(float4*)&tot[i][0];
    }
}

// ---------------- phase 2: CH-step LIF chunk, segmented float4 gather --------
#define NT    512
#define W4ROW 517            // 2068 / 4 float4s per W_rec row

__device__ __forceinline__ float4 f4add(float4 a, float4 b) {
    return make_float4(__fadd_rn(a.x, b.x), __fadd_rn(a.y, b.y),
                       __fadd_rn(a.z, b.z), __fadd_rn(a.w, b.w));
}

__global__ __launch_bounds__(NT, 2) void steps_kernel(const float* __restrict__ Wrec,
                                                      float* __restrict__ out, int t0) {
    __shared__ int s_list[NN];
    __shared__ int s_wcnt[16];
    __shared__ int s_tcnt;
    __shared__ int s_seg[NSEG];

    int b    = blockIdx.x;
    int tid  = threadIdx.x;
    int wid  = tid >> 5;
    int lane = tid & 31;
    unsigned ltmask = (1u << lane) - 1u;
    bool tv  = (tid < NOUT);

    const float4* W4 = (const float4*)Wrec;
    size_t sb  = (size_t)b * NNP;
    size_t sb4 = sb >> 2;

    float4 mv, sv;
    float  mt, st;
    if (t0 == 0) {
        mv = make_float4(0.f, 0.f, 0.f, 0.f);
        sv = make_float4(0.f, 0.f, 0.f, 0.f);
        mt = 0.f; st = 0.f;
    } else {
        mv = ((const float4*)g_mem)[sb4 + tid];
        sv = ((const float4*)g_spk)[sb4 + tid];
        mt = tv ? g_mem[sb + 2048 + tid] : 0.f;
        st = tv ? g_spk[sb + 2048 + tid] : 0.f;
    }

    for (int t = t0; t < t0 + CH; t++) {
        // ---- ff load (already panel-folded by GEMM) ----
        size_t rbase = ((size_t)t * B_ + b) * NNP;
        float4 ffv = ((const float4*)g_ff)[(rbase >> 2) + tid];
        float  fft = tv ? g_ff[rbase + 2048 + tid] : 0.f;

        // ---- compaction: 4-bit mask + warp scan + cross-warp prefix ----
        unsigned am = (sv.x != 0.f ? 1u : 0u) | (sv.y != 0.f ? 2u : 0u)
                    | (sv.z != 0.f ? 4u : 0u) | (sv.w != 0.f ? 8u : 0u);
        int nact = __popc(am);
        int scan = nact;
        #pragma unroll
        for (int d = 1; d < 32; d <<= 1) {
            int o = __shfl_up_sync(0xffffffffu, scan, d);
            if (lane >= d) scan += o;
        }
        if (lane == 31) s_wcnt[wid] = scan;

        bool ta = tv && (st != 0.f);
        unsigned tmask = __ballot_sync(0xffffffffu, ta);   // valid in warp 0
        if (tid == 0) s_tcnt = __popc(tmask);
        __syncthreads();

        int vbase = 0, vtotal = 0;
        #pragma unroll
        for (int w = 0; w < 16; w++) {
            int c = s_wcnt[w];
            if (w < wid) vbase += c;
            vtotal += c;
        }
        int pos = vbase + (scan - nact);
        if (am & 1u) s_list[pos++] = 4 * tid + 0;
        if (am & 2u) s_list[pos++] = 4 * tid + 1;
        if (am & 4u) s_list[pos++] = 4 * tid + 2;
        if (am & 8u) s_list[pos++] = 4 * tid + 3;
        if (ta) s_list[vtotal + __popc(tmask & ltmask)] = 2048 + tid;
        __syncthreads();

        int cnt = vtotal + s_tcnt;

        // ---- segment boundaries: lower_bound of (p+1)*320 in s_list ----
        if (tid < NSEG) {
            int target = (tid + 1) * KC;
            int lo = 0, hi = cnt;
            while (lo < hi) {
                int mid = (lo + hi) >> 1;
                if (s_list[mid] < target) lo = mid + 1; else hi = mid;
            }
            s_seg[tid] = lo;
        }
        __syncthreads();

        // ---- rec: per-segment plain adds, fold between segments ----
        float4 rec  = make_float4(0.f, 0.f, 0.f, 0.f);
        float  rect = 0.f;

        int start = 0;
        #pragma unroll 1
        for (int p = 0; p < NSEG; p++) {
            int end = s_seg[p];
            float4 part = make_float4(0.f, 0.f, 0.f, 0.f);
            float  partt = 0.f;
            int i = start;
            for (; i + 4 <= end; i += 4) {
                int m0 = s_list[i + 0], m1 = s_list[i + 1];
                int m2 = s_list[i + 2], m3 = s_list[i + 3];
                float4 v0 = W4[(size_t)m0 * W4ROW + tid];
                float4 v1 = W4[(size_t)m1 * W4ROW + tid];
                float4 v2 = W4[(size_t)m2 * W4ROW + tid];
                float4 v3 = W4[(size_t)m3 * W4ROW + tid];
                float  t0s = tv ? Wrec[(size_t)m0 * NN + 2048 + tid] : 0.f;
                float  t1s = tv ? Wrec[(size_t)m1 * NN + 2048 + tid] : 0.f;
                float  t2s = tv ? Wrec[(size_t)m2 * NN + 2048 + tid] : 0.f;
                float  t3s = tv ? Wrec[(size_t)m3 * NN + 2048 + tid] : 0.f;
                part = f4add(part, v0); partt = __fadd_rn(partt, t0s);
                part = f4add(part, v1); partt = __fadd_rn(partt, t1s);
                part = f4add(part, v2); partt = __fadd_rn(partt, t2s);
                part = f4add(part, v3); partt = __fadd_rn(partt, t3s);
            }
            for (; i < end; i++) {
                int mr = s_list[i];
                float4 v0 = W4[(size_t)mr * W4ROW + tid];
                float  t0s = tv ? Wrec[(size_t)mr * NN + 2048 + tid] : 0.f;
                part = f4add(part, v0); partt = __fadd_rn(partt, t0s);
            }
            rec  = f4add(rec, part);            // fadd(x,+0) == x for empty segs
            rect = __fadd_rn(rect, partt);
            start = end;
        }

        // ---- membrane update + spikes (unfused, reference order) ----
        {
            float4 cur = f4add(ffv, rec);
            mv = make_float4(
                __fadd_rn(__fmul_rn(__fmul_rn(TAU, mv.x), __fsub_rn(1.f, sv.x)), cur.x),
                __fadd_rn(__fmul_rn(__fmul_rn(TAU, mv.y), __fsub_rn(1.f, sv.y)), cur.y),
                __fadd_rn(__fmul_rn(__fmul_rn(TAU, mv.z), __fsub_rn(1.f, sv.z)), cur.z),
                __fadd_rn(__fmul_rn(__fmul_rn(TAU, mv.w), __fsub_rn(1.f, sv.w)), cur.w));
            sv = make_float4(mv.x >= 1.f ? 1.f : 0.f, mv.y >= 1.f ? 1.f : 0.f,
                             mv.z >= 1.f ? 1.f : 0.f, mv.w >= 1.f ? 1.f : 0.f);
        }
        if (tv) {
            float cur = __fadd_rn(fft, rect);
            mt = __fadd_rn(__fmul_rn(__fmul_rn(TAU, mt), __fsub_rn(1.f, st)), cur);
            st = (mt >= 1.f) ? 1.f : 0.f;
            out[((size_t)b * T_ + t) * NOUT + tid] = st;
        }

        __syncthreads();   // protect s_list/s_wcnt/s_seg reuse next step
    }

    // ---- park state for next chunk ----
    ((float4*)g_mem)[sb4 + tid] = mv;
    ((float4*)g_spk)[sb4 + tid] = sv;
    if (tv) {
        g_mem[sb + 2048 + tid] = mt;
        g_spk[sb + 2048 + tid] = st;
    }
}

// ---------------- launch: prioritized stream-forked chunk pipeline -----------
extern "C" void kernel_launch(void* const* d_in, const int* in_sizes, int n_in,
                              void* d_out, int out_size) {
    const float* x  = (const float*)d_in[0];   // [B, T, NIN]
    const float* W1 = (const float*)d_in[1];   // [NN, NIN]
    const float* Wr = (const float*)d_in[2];   // [NN, NN]
    float* out = (float*)d_out;                // [B, T, NOUT]

    // staging on origin stream
    {
        size_t n = (size_t)MROWS * KP;
        pad_x_kernel<<<(unsigned)((n + 255) / 256), 256>>>(x);
    }
    {
        size_t n = (size_t)KP * NNP;
        pad_w1t_kernel<<<(unsigned)((n + 255) / 256), 256>>>(W1);
    }
    cudaEventRecord(g_ctx.evStage, 0);

    // GEMM chunks on low-priority stream sG
    cudaStreamWaitEvent(g_ctx.sG, g_ctx.evStage, 0);
    dim3 ggrid(NCOLB, RPC / BM);               // 33 x 20 per chunk
    for (int c = 0; c < NCH; c++) {
        gemm_fold_kernel<<<ggrid, 256, 0, g_ctx.sG>>>(c * RPC);
        cudaEventRecord(g_ctx.evG[c], g_ctx.sG);
    }

    // steps chunks on high-priority stream sS, each gated on its GEMM chunk
    for (int c = 0; c < NCH; c++) {
        cudaStreamWaitEvent(g_ctx.sS, g_ctx.evG[c], 0);
        steps_kernel<<<B_, NT, 0, g_ctx.sS>>>(Wr, out, c * CH);
    }

    // join forked work back to the origin stream (graph-capture requirement)
    cudaEventRecord(g_ctx.evJoin, g_ctx.sS);
    cudaStreamWaitEvent(0, g_ctx.evJoin, 0);
}